// round 1
// baseline (speedup 1.0000x reference)
#include <cuda_runtime.h>
#include <math.h>
#include <stdint.h>

#define NTOK 16384
#define DIM  512
#define MDIM 1024
#define NEXP 8
#define TOPK 2
#define NSLOTS (NTOK * TOPK)   // 32768

// ---------------- scratch (device globals; no allocation in kernel_launch) ---
__device__ float g_H[(size_t)NSLOTS * MDIM];   // 134 MB: gelu(x@W1+b1) per slot
__device__ int   g_rows_token[NSLOTS];
__device__ float g_rows_gate[NSLOTS];
__device__ int   g_counts[NEXP];
__device__ int   g_offsets[NEXP + 1];
__device__ int   g_pos[NEXP];
__device__ float g_importance[NEXP];
__device__ int   g_expert_idx[NTOK * TOPK];
__device__ float g_gate_val[NTOK * TOPK];

// ---------------- small init --------------------------------------------------
__global__ void zero_small_kernel() {
    int t = threadIdx.x;
    if (t < NEXP) {
        g_counts[t] = 0;
        g_pos[t] = 0;
        g_importance[t] = 0.f;
    }
}

// ---------------- gating: logits, top-2, softmax, stats ----------------------
__global__ void gating_kernel(const float* __restrict__ x,
                              const float* __restrict__ w_gate) {
    __shared__ float ws[DIM * NEXP];   // 16 KB
    const int tid = threadIdx.x;
    for (int i = tid; i < DIM * NEXP; i += blockDim.x) ws[i] = w_gate[i];
    __syncthreads();

    const int warp = tid >> 5;
    const int lane = tid & 31;
    const int n = blockIdx.x * 8 + warp;
    if (n >= NTOK) return;

    float acc[NEXP];
#pragma unroll
    for (int e = 0; e < NEXP; e++) acc[e] = 0.f;

    const float* xr = x + (size_t)n * DIM;
    for (int d = lane; d < DIM; d += 32) {
        float xv = xr[d];
#pragma unroll
        for (int e = 0; e < NEXP; e++)
            acc[e] = fmaf(xv, ws[d * NEXP + e], acc[e]);
    }
#pragma unroll
    for (int s = 16; s > 0; s >>= 1) {
#pragma unroll
        for (int e = 0; e < NEXP; e++)
            acc[e] += __shfl_xor_sync(0xffffffffu, acc[e], s);
    }

    if (lane == 0) {
        // top-2, ties -> lowest index (matches jax.lax.top_k stability)
        int i1 = 0; float v1 = acc[0];
#pragma unroll
        for (int e = 1; e < NEXP; e++)
            if (acc[e] > v1) { v1 = acc[e]; i1 = e; }
        int i2 = -1; float v2 = -INFINITY;
#pragma unroll
        for (int e = 0; e < NEXP; e++)
            if (e != i1 && acc[e] > v2) { v2 = acc[e]; i2 = e; }

        // softmax over [v1, v2] (v1 is max): g1 = 1/(1+exp(v2-v1))
        float e1 = expf(v2 - v1);
        float inv = 1.f / (1.f + e1);
        float gA = inv;
        float gB = e1 * inv;

        g_expert_idx[n * 2 + 0] = i1;
        g_expert_idx[n * 2 + 1] = i2;
        g_gate_val[n * 2 + 0] = gA;
        g_gate_val[n * 2 + 1] = gB;

        atomicAdd(&g_importance[i1], gA);
        atomicAdd(&g_importance[i2], gB);
        atomicAdd(&g_counts[i1], 1);
        atomicAdd(&g_counts[i2], 1);
    }
}

// ---------------- offsets + aux loss ------------------------------------------
__global__ void offsets_loss_kernel(float* __restrict__ loss_ptr) {
    if (threadIdx.x != 0) return;
    int off = 0;
    for (int e = 0; e < NEXP; e++) {
        g_offsets[e] = off;
        g_pos[e] = off;
        off += g_counts[e];
    }
    g_offsets[NEXP] = off;

    float mi = 0.f, ml = 0.f;
    for (int e = 0; e < NEXP; e++) { mi += g_importance[e]; ml += (float)g_counts[e]; }
    mi *= (1.f / NEXP); ml *= (1.f / NEXP);
    float vi = 0.f, vl = 0.f;
    for (int e = 0; e < NEXP; e++) {
        float di = g_importance[e] - mi; vi += di * di;
        float dl = (float)g_counts[e] - ml; vl += dl * dl;
    }
    vi *= (1.f / (NEXP - 1));
    vl *= (1.f / (NEXP - 1));
    float loss = 0.01f * (vi / (mi * mi + 1e-10f) + vl / (ml * ml + 1e-10f));
    *loss_ptr = loss;
}

// ---------------- scatter: build per-expert compact rows ----------------------
__global__ void scatter_kernel() {
    int n = blockIdx.x * blockDim.x + threadIdx.x;
    if (n >= NTOK) return;
#pragma unroll
    for (int s = 0; s < TOPK; s++) {
        int e = g_expert_idx[n * 2 + s];
        int p = atomicAdd(&g_pos[e], 1);
        g_rows_token[p] = n;
        g_rows_gate[p] = g_gate_val[n * 2 + s];
    }
}

// ---------------- GEMM1: H = gelu(X_e @ W1[e] + b1[e]) ------------------------
// block tile 128(rows) x 128(m), BK=16, 256 threads, 8x8 per thread
__global__ void __launch_bounds__(256, 2)
gemm1_kernel(const float* __restrict__ x,
             const float* __restrict__ W1,
             const float* __restrict__ b1p) {
    const int e = blockIdx.z;
    const int c = g_counts[e];
    const int rbase = blockIdx.y * 128;
    if (rbase >= c) return;
    const int mbase = blockIdx.x * 128;
    const int off = g_offsets[e];
    const float* W = W1 + (size_t)e * DIM * MDIM;

    __shared__ float Ast[16][132];   // [k][row], padded
    __shared__ float Bs[16][128];    // [k][m]
    __shared__ int toks[128];

    const int tid = threadIdx.x;
    if (tid < 128) {
        int r = rbase + tid;
        toks[tid] = (r < c) ? g_rows_token[off + r] : -1;
    }
    __syncthreads();

    const int ty = tid >> 4;   // 0..15 -> rows ty*8..ty*8+7
    const int tx = tid & 15;   // 0..15 -> cols tx*8..tx*8+7

    float acc[8][8];
#pragma unroll
    for (int i = 0; i < 8; i++)
#pragma unroll
        for (int j = 0; j < 8; j++) acc[i][j] = 0.f;

    for (int k0 = 0; k0 < DIM; k0 += 16) {
        // A tile: 128 rows x 16 k = 512 float4, 2 per thread
#pragma unroll
        for (int l = 0; l < 2; l++) {
            int idx = tid + l * 256;
            int r = idx >> 2;
            int k4 = (idx & 3) * 4;
            int t = toks[r];
            float4 v = make_float4(0.f, 0.f, 0.f, 0.f);
            if (t >= 0)
                v = *reinterpret_cast<const float4*>(x + (size_t)t * DIM + k0 + k4);
            Ast[k4 + 0][r] = v.x;
            Ast[k4 + 1][r] = v.y;
            Ast[k4 + 2][r] = v.z;
            Ast[k4 + 3][r] = v.w;
        }
        // B tile: 16 k x 128 m = 512 float4, 2 per thread
#pragma unroll
        for (int l = 0; l < 2; l++) {
            int idx = tid + l * 256;
            int kr = idx >> 5;
            int m4 = (idx & 31) * 4;
            *reinterpret_cast<float4*>(&Bs[kr][m4]) =
                *reinterpret_cast<const float4*>(W + (size_t)(k0 + kr) * MDIM + mbase + m4);
        }
        __syncthreads();
#pragma unroll
        for (int kk = 0; kk < 16; kk++) {
            float4 a0 = *reinterpret_cast<float4*>(&Ast[kk][ty * 8]);
            float4 a1 = *reinterpret_cast<float4*>(&Ast[kk][ty * 8 + 4]);
            float4 b0 = *reinterpret_cast<float4*>(&Bs[kk][tx * 8]);
            float4 b1v = *reinterpret_cast<float4*>(&Bs[kk][tx * 8 + 4]);
            float a[8] = {a0.x, a0.y, a0.z, a0.w, a1.x, a1.y, a1.z, a1.w};
            float b[8] = {b0.x, b0.y, b0.z, b0.w, b1v.x, b1v.y, b1v.z, b1v.w};
#pragma unroll
            for (int i = 0; i < 8; i++)
#pragma unroll
                for (int j = 0; j < 8; j++)
                    acc[i][j] = fmaf(a[i], b[j], acc[i][j]);
        }
        __syncthreads();
    }

    float bias[8];
#pragma unroll
    for (int j = 0; j < 8; j++) bias[j] = b1p[e * MDIM + mbase + tx * 8 + j];

#pragma unroll
    for (int i = 0; i < 8; i++) {
        int r = rbase + ty * 8 + i;
        if (r >= c) continue;
        float* Hrow = g_H + (size_t)(off + r) * MDIM + mbase + tx * 8;
        float o[8];
#pragma unroll
        for (int j = 0; j < 8; j++) {
            float v = acc[i][j] + bias[j];
            o[j] = 0.5f * v * (1.f + erff(v * 0.70710678118654752f));  // exact gelu
        }
        *reinterpret_cast<float4*>(Hrow) = make_float4(o[0], o[1], o[2], o[3]);
        *reinterpret_cast<float4*>(Hrow + 4) = make_float4(o[4], o[5], o[6], o[7]);
    }
}

// ---------------- GEMM2: y += gate * (H_e @ W2[e] + b2[e]) --------------------
__global__ void __launch_bounds__(256, 2)
gemm2_kernel(const float* __restrict__ W2,
             const float* __restrict__ b2p,
             float* __restrict__ y) {
    const int e = blockIdx.z;
    const int c = g_counts[e];
    const int rbase = blockIdx.y * 128;
    if (rbase >= c) return;
    const int nbase = blockIdx.x * 128;
    const int off = g_offsets[e];
    const float* W = W2 + (size_t)e * MDIM * DIM;

    __shared__ float Ast[16][132];
    __shared__ float Bs[16][128];

    const int tid = threadIdx.x;
    const int ty = tid >> 4;
    const int tx = tid & 15;

    float acc[8][8];
#pragma unroll
    for (int i = 0; i < 8; i++)
#pragma unroll
        for (int j = 0; j < 8; j++) acc[i][j] = 0.f;

    for (int k0 = 0; k0 < MDIM; k0 += 16) {
        // A tile from H: 128 rows x 16 k
#pragma unroll
        for (int l = 0; l < 2; l++) {
            int idx = tid + l * 256;
            int r = idx >> 2;
            int k4 = (idx & 3) * 4;
            int rr = rbase + r;
            float4 v = make_float4(0.f, 0.f, 0.f, 0.f);
            if (rr < c)
                v = *reinterpret_cast<const float4*>(g_H + (size_t)(off + rr) * MDIM + k0 + k4);
            Ast[k4 + 0][r] = v.x;
            Ast[k4 + 1][r] = v.y;
            Ast[k4 + 2][r] = v.z;
            Ast[k4 + 3][r] = v.w;
        }
        // B tile: W2[e][k][d], stride DIM
#pragma unroll
        for (int l = 0; l < 2; l++) {
            int idx = tid + l * 256;
            int kr = idx >> 5;
            int m4 = (idx & 31) * 4;
            *reinterpret_cast<float4*>(&Bs[kr][m4]) =
                *reinterpret_cast<const float4*>(W + (size_t)(k0 + kr) * DIM + nbase + m4);
        }
        __syncthreads();
#pragma unroll
        for (int kk = 0; kk < 16; kk++) {
            float4 a0 = *reinterpret_cast<float4*>(&Ast[kk][ty * 8]);
            float4 a1 = *reinterpret_cast<float4*>(&Ast[kk][ty * 8 + 4]);
            float4 b0 = *reinterpret_cast<float4*>(&Bs[kk][tx * 8]);
            float4 b1v = *reinterpret_cast<float4*>(&Bs[kk][tx * 8 + 4]);
            float a[8] = {a0.x, a0.y, a0.z, a0.w, a1.x, a1.y, a1.z, a1.w};
            float b[8] = {b0.x, b0.y, b0.z, b0.w, b1v.x, b1v.y, b1v.z, b1v.w};
#pragma unroll
            for (int i = 0; i < 8; i++)
#pragma unroll
                for (int j = 0; j < 8; j++)
                    acc[i][j] = fmaf(a[i], b[j], acc[i][j]);
        }
        __syncthreads();
    }

    float bias[8];
#pragma unroll
    for (int j = 0; j < 8; j++) bias[j] = b2p[e * DIM + nbase + tx * 8 + j];

#pragma unroll
    for (int i = 0; i < 8; i++) {
        int r = rbase + ty * 8 + i;
        if (r >= c) continue;
        int slot = off + r;
        int tok = g_rows_token[slot];
        float g = g_rows_gate[slot];
        float* yrow = y + (size_t)tok * DIM + nbase + tx * 8;
#pragma unroll
        for (int j = 0; j < 8; j++) {
            float v = acc[i][j] + bias[j];
            atomicAdd(&yrow[j], g * v);
        }
    }
}

// ---------------- launch -------------------------------------------------------
extern "C" void kernel_launch(void* const* d_in, const int* in_sizes, int n_in,
                              void* d_out, int out_size) {
    const float* x      = (const float*)d_in[0];
    const float* w_gate = (const float*)d_in[1];
    const float* W1     = (const float*)d_in[2];
    const float* b1     = (const float*)d_in[3];
    const float* W2     = (const float*)d_in[4];
    const float* b2     = (const float*)d_in[5];
    float* out = (float*)d_out;

    // y (and loss slot) start from zero every replay
    cudaMemsetAsync(d_out, 0, (size_t)out_size * sizeof(float));
    zero_small_kernel<<<1, 32>>>();

    gating_kernel<<<NTOK / 8, 256>>>(x, w_gate);
    offsets_loss_kernel<<<1, 1>>>(out + (out_size - 1));   // loss after y
    scatter_kernel<<<NTOK / 256, 256>>>();

    dim3 g1(MDIM / 128, NTOK / 128, NEXP);   // (8, 128, 8)
    gemm1_kernel<<<g1, 256>>>(x, W1, b1);

    dim3 g2(DIM / 128, NTOK / 128, NEXP);    // (4, 128, 8)
    gemm2_kernel<<<g2, 256>>>(W2, b2, out);
}